// round 5
// baseline (speedup 1.0000x reference)
#include <cuda_runtime.h>
#include <cuda_bf16.h>
#include <math.h>
#include <stdint.h>

// ---------------- problem constants ----------------
#define BATCH 32
#define DEPTH 11
#define NNODES 2047
#define MD 300
#define KDIM 300
#define KPAD 320
#define KT 10                 // KPAD / 32 stages
#define LEAF_BASE 1023
#define LEAF_CNT 1024
#define TOTAL_ROWS (BATCH * NNODES)   // 65504
#define MAXSUM (BATCH * 512)          // 16384 max level rows

// ---------------- GEMM tile ----------------
#define BM 128
#define BN 128
// smem stage layout (bytes)
#define OFF_AHI 0
#define OFF_ALO 10240
#define OFF_BHI 20480
#define OFF_BLO 29184
#define STAGE_B 37888
#define SMEM_G (3 * STAGE_B)   // 113664

// padded N strides of packed weights
#define NP_X 1280
#define NP_H 1024
#define NP_F 384

typedef __nv_bfloat16 bf16;

// ---------------- device scratch ----------------
__device__ float g_gates_x[(size_t)TOTAL_ROWS * 1200];
__device__ float g_c[(size_t)TOTAL_ROWS * MD];
__device__ float g_iou[(size_t)MAXSUM * 900];
__device__ float g_f[(size_t)(2 * MAXSUM) * 300];
__device__ float g_bx[1200];

__device__ __align__(16) bf16 g_embh[(size_t)TOTAL_ROWS * KPAD];
__device__ __align__(16) bf16 g_embl[(size_t)TOTAL_ROWS * KPAD];
__device__ __align__(16) bf16 g_hh[(size_t)TOTAL_ROWS * KPAD];
__device__ __align__(16) bf16 g_hl[(size_t)TOTAL_ROWS * KPAD];
__device__ __align__(16) bf16 g_sumh[(size_t)MAXSUM * KPAD];
__device__ __align__(16) bf16 g_suml[(size_t)MAXSUM * KPAD];
__device__ __align__(16) bf16 g_Wxh[(size_t)KPAD * NP_X];
__device__ __align__(16) bf16 g_Wxl[(size_t)KPAD * NP_X];
__device__ __align__(16) bf16 g_Whh[(size_t)KPAD * NP_H];
__device__ __align__(16) bf16 g_Whl[(size_t)KPAD * NP_H];
__device__ __align__(16) bf16 g_Wfh[(size_t)KPAD * NP_F];
__device__ __align__(16) bf16 g_Wfl[(size_t)KPAD * NP_F];

__device__ __forceinline__ float sigmoidf(float x) {
    return 1.0f / (1.0f + expf(-x));
}
__device__ __forceinline__ void split_bf16(float v, bf16& hi, bf16& lo) {
    hi = __float2bfloat16(v);
    lo = __float2bfloat16(v - __bfloat162float(hi));
}

// ---------------- ptx helpers ----------------
__device__ __forceinline__ uint32_t smem_u32(const void* p) {
    uint32_t a;
    asm("{ .reg .u64 t; cvta.to.shared.u64 t, %1; cvt.u32.u64 %0, t; }" : "=r"(a) : "l"(p));
    return a;
}
__device__ __forceinline__ void cp16(uint32_t dst, const void* src, int sz) {
    asm volatile("cp.async.cg.shared.global [%0], [%1], 16, %2;"
                 :: "r"(dst), "l"(src), "r"(sz));
}
__device__ __forceinline__ void cp_commit() { asm volatile("cp.async.commit_group;"); }
__device__ __forceinline__ void ldsm4(unsigned* r, uint32_t a) {
    asm volatile("ldmatrix.sync.aligned.m8n8.x4.shared.b16 {%0,%1,%2,%3}, [%4];"
                 : "=r"(r[0]), "=r"(r[1]), "=r"(r[2]), "=r"(r[3]) : "r"(a));
}
__device__ __forceinline__ void ldsm4t(unsigned* r, uint32_t a) {
    asm volatile("ldmatrix.sync.aligned.m8n8.x4.trans.shared.b16 {%0,%1,%2,%3}, [%4];"
                 : "=r"(r[0]), "=r"(r[1]), "=r"(r[2]), "=r"(r[3]) : "r"(a));
}
__device__ __forceinline__ void mma16816(float* d, const unsigned* a, const unsigned* b) {
    asm volatile(
        "mma.sync.aligned.m16n8k16.row.col.f32.bf16.bf16.f32 "
        "{%0,%1,%2,%3}, {%4,%5,%6,%7}, {%8,%9}, {%0,%1,%2,%3};"
        : "+f"(d[0]), "+f"(d[1]), "+f"(d[2]), "+f"(d[3])
        : "r"(a[0]), "r"(a[1]), "r"(a[2]), "r"(a[3]), "r"(b[0]), "r"(b[1]));
}

// ---------------- weight packing: [k][n] bf16 hi/lo, padded, zero-filled ----------------
__global__ void pack_kernel(
    const float* __restrict__ Wix, const float* __restrict__ Wfx,
    const float* __restrict__ Wox, const float* __restrict__ Wux,
    const float* __restrict__ bix, const float* __restrict__ bfx,
    const float* __restrict__ box_, const float* __restrict__ bux,
    const float* __restrict__ Wih, const float* __restrict__ Woh,
    const float* __restrict__ Wuh, const float* __restrict__ Wfh)
{
    const int i = blockIdx.x * blockDim.x + threadIdx.x;
    if (i < KPAD * NP_X) {
        const int k = i / NP_X, n = i % NP_X;
        float v = 0.0f;
        if (k < KDIM && n < 1200) {
            const int g = n / 300, j = n % 300;
            const float* W = (g == 0) ? Wix : (g == 1) ? Wfx : (g == 2) ? Wox : Wux;
            v = W[k * 300 + j];
        }
        split_bf16(v, g_Wxh[i], g_Wxl[i]);
    }
    if (i < KPAD * NP_H) {
        const int k = i / NP_H, n = i % NP_H;
        float v = 0.0f;
        if (k < KDIM && n < 900) {
            const int g = n / 300, j = n % 300;
            const float* W = (g == 0) ? Wih : (g == 1) ? Woh : Wuh;
            v = W[k * 300 + j];
        }
        split_bf16(v, g_Whh[i], g_Whl[i]);
    }
    if (i < KPAD * NP_F) {
        const int k = i / NP_F, n = i % NP_F;
        float v = (k < KDIM && n < 300) ? Wfh[k * 300 + n] : 0.0f;
        split_bf16(v, g_Wfh[i], g_Wfl[i]);
    }
    if (i < 1200) {
        const int g = i / 300, j = i % 300;
        const float* bb = (g == 0) ? bix : (g == 1) ? bfx : (g == 2) ? box_ : bux;
        g_bx[i] = bb[j];
    }
}

// ---------------- embs -> bf16 hi/lo, padded ----------------
__global__ void convert_embs(const float* __restrict__ embs) {
    const long idx = (long)blockIdx.x * blockDim.x + threadIdx.x;
    if (idx >= (long)TOTAL_ROWS * KPAD) return;
    const long row = idx / KPAD;
    const int k = (int)(idx % KPAD);
    const float v = (k < KDIM) ? embs[row * KDIM + k] : 0.0f;
    split_bf16(v, g_embh[idx], g_embl[idx]);
}

// ---------------- per-level child-sum + split ----------------
__global__ void sumsplit_kernel(const float* __restrict__ h, int l) {
    const int nl = 1 << l;
    const int Mh = BATCH << l;
    const int total = Mh * MD;
    const int idx = blockIdx.x * blockDim.x + threadIdx.x;
    if (idx >= total) return;
    const int j = idx % MD;
    const int r = idx / MD;
    const int b = r >> l;
    const int t = r & (nl - 1);
    const int node = (nl - 1) + t;
    const size_t c1 = ((size_t)b * NNODES + 2 * node + 1) * MD;
    const float s = h[c1 + j] + h[c1 + MD + j];
    split_bf16(s, g_sumh[(size_t)r * KPAD + j], g_suml[(size_t)r * KPAD + j]);
}

// ---------------- bf16x3 HMMA GEMM with fused A-gather ----------------
// C[M,N] = A[M,KPAD] @ B[KPAD,N]  (A,B split hi/lo bf16; B row stride NP)
// mode 0: A row = grow * KPAD
// mode 2: A row = h split row of child(1 or 2) at level level_l (stacked)
__global__ __launch_bounds__(256, 1) void gemm_mma(
    const bf16* __restrict__ Ah, const bf16* __restrict__ Al,
    const bf16* __restrict__ Bh, const bf16* __restrict__ Bl,
    float* __restrict__ C, const float* __restrict__ bias,
    int M, int N, int NP, int ldc, int mode, int level_l)
{
    extern __shared__ __align__(128) char smem[];
    const uint32_t sbase = smem_u32(smem);
    const int tid = threadIdx.x;
    const int lane = tid & 31;
    const int wid = tid >> 5;
    const int wm = wid & 3;           // 4 m-warps * 32 rows
    const int wn = wid >> 2;          // 2 n-warps * 64 cols
    const int m_base = blockIdx.y * BM;
    const int n_base = blockIdx.x * BN;

    // ---- staging source offsets ----
    const int c4 = tid & 3;                 // A 16B chunk within 64B row-slab
    const int ar0 = tid >> 2;               // A rows: ar0, ar0+64
    size_t aoff[2]; int asz[2];
#pragma unroll
    for (int i = 0; i < 2; i++) {
        const int grow = m_base + ar0 + i * 64;
        const bool ok = grow < M;
        size_t off = 0;
        if (ok) {
            if (mode == 0) {
                off = (size_t)grow * KPAD;
            } else {
                const int nl = 1 << level_l;
                const int Mh = BATCH << level_l;
                int rr = grow, sel = 0;
                if (grow >= Mh) { sel = 1; rr -= Mh; }
                const int b = rr >> level_l;
                const int t = rr & (nl - 1);
                const int node = (nl - 1) + t;
                off = ((size_t)b * NNODES + 2 * node + 1 + sel) * KPAD;
            }
        }
        aoff[i] = off; asz[i] = ok ? 16 : 0;
    }
    const int cb = tid & 15;                // B 16B chunk (8 n) within 256B row
    const int br0 = tid >> 4;               // B k-rows: br0, br0+16
    const int bn0 = n_base + cb * 8;

    // ---- ldmatrix lane address components ----
    const uint32_t a_lane = (uint32_t)((lane & 15) * 80 + (lane >> 4) * 16);
    const int jj = lane >> 3, r8 = lane & 7;
    const uint32_t b_lane = (uint32_t)(((jj & 1) * 8 + r8) * 272 + (jj >> 1) * 16);

    float acc[2][8][4];
#pragma unroll
    for (int a = 0; a < 2; a++)
#pragma unroll
        for (int b = 0; b < 8; b++)
#pragma unroll
            for (int c = 0; c < 4; c++) acc[a][b][c] = 0.0f;

    // ---- stage helper ----
    auto stage = [&](int t, int buf) {
        const uint32_t sb = sbase + buf * STAGE_B;
        const int k0 = t * 32;
#pragma unroll
        for (int i = 0; i < 2; i++) {
            const int row = ar0 + i * 64;
            const size_t so = aoff[i] + k0 + c4 * 8;
            const uint32_t d = sb + row * 80 + c4 * 16;
            cp16(d + OFF_AHI, Ah + so, asz[i]);
            cp16(d + OFF_ALO, Al + so, asz[i]);
        }
#pragma unroll
        for (int i = 0; i < 2; i++) {
            const int kr = br0 + i * 16;
            const size_t so = (size_t)(k0 + kr) * NP + bn0;
            const uint32_t d = sb + kr * 272 + cb * 16;
            cp16(d + OFF_BHI, Bh + so, 16);
            cp16(d + OFF_BLO, Bl + so, 16);
        }
    };

    // ---- 3-stage pipeline ----
    stage(0, 0); cp_commit();
    stage(1, 1); cp_commit();

    for (int t = 0; t < KT; ++t) {
        asm volatile("cp.async.wait_group 1;" ::: "memory");
        __syncthreads();
        if (t + 2 < KT) stage(t + 2, (t + 2) % 3);
        cp_commit();

        const uint32_t sb = sbase + (t % 3) * STAGE_B;
#pragma unroll
        for (int k16 = 0; k16 < 2; k16++) {
            unsigned ah[2][4], al[2][4], bh[8][2], bl[8][2];
#pragma unroll
            for (int tm = 0; tm < 2; tm++) {
                const uint32_t ad = sb + (wm * 32 + tm * 16) * 80 + k16 * 32 + a_lane;
                ldsm4(ah[tm], ad + OFF_AHI);
                ldsm4(al[tm], ad + OFF_ALO);
            }
#pragma unroll
            for (int p = 0; p < 4; p++) {
                const uint32_t bd = sb + (uint32_t)(k16 * 16 * 272) +
                                    (uint32_t)((wn * 64 + p * 16) * 2) + b_lane;
                unsigned r[4];
                ldsm4t(r, bd + OFF_BHI);
                bh[2 * p][0] = r[0]; bh[2 * p][1] = r[1];
                bh[2 * p + 1][0] = r[2]; bh[2 * p + 1][1] = r[3];
                ldsm4t(r, bd + OFF_BLO);
                bl[2 * p][0] = r[0]; bl[2 * p][1] = r[1];
                bl[2 * p + 1][0] = r[2]; bl[2 * p + 1][1] = r[3];
            }
#pragma unroll
            for (int tm = 0; tm < 2; tm++)
#pragma unroll
                for (int tn = 0; tn < 8; tn++) {
                    mma16816(acc[tm][tn], ah[tm], bh[tn]);
                    mma16816(acc[tm][tn], ah[tm], bl[tn]);
                    mma16816(acc[tm][tn], al[tm], bh[tn]);
                }
        }
    }

    // ---- epilogue: registers -> C ----
    const int mrow = lane >> 2;
    const int ncol = (lane & 3) * 2;
#pragma unroll
    for (int tm = 0; tm < 2; tm++) {
#pragma unroll
        for (int half = 0; half < 2; half++) {
            const int gm = m_base + wm * 32 + tm * 16 + half * 8 + mrow;
            if (gm >= M) continue;
            float* crow = C + (size_t)gm * ldc;
#pragma unroll
            for (int tn = 0; tn < 8; tn++) {
                const int gn = n_base + wn * 64 + tn * 8 + ncol;
                if (gn < N) {
                    float v0 = acc[tm][tn][half * 2];
                    float v1 = acc[tm][tn][half * 2 + 1];
                    if (bias) { v0 += bias[gn]; v1 += bias[gn + 1]; }
                    crow[gn] = v0;
                    crow[gn + 1] = v1;
                }
            }
        }
    }
}

// ---------------- pointwise: leaves (+ h split) ----------------
__global__ void leaf_kernel(float* __restrict__ h,
                            const float* __restrict__ bih,
                            const float* __restrict__ boh,
                            const float* __restrict__ buh)
{
    const int idx = blockIdx.x * blockDim.x + threadIdx.x;
    const int total = BATCH * LEAF_CNT * MD;
    if (idx >= total) return;
    const int j = idx % MD;
    const int rn = idx / MD;
    const int node = LEAF_BASE + (rn & (LEAF_CNT - 1));
    const int b = rn >> 10;
    const size_t rowx = (size_t)b * NNODES + node;
    const float* gx = g_gates_x + rowx * 1200;
    const float i = sigmoidf(gx[j] + bih[j]);
    const float o = sigmoidf(gx[600 + j] + boh[j]);
    const float u = tanhf(gx[900 + j] + buh[j]);
    const float c = i * u;
    const float hv = o * tanhf(c);
    g_c[rowx * MD + j] = c;
    h[rowx * MD + j] = hv;
    split_bf16(hv, g_hh[rowx * KPAD + j], g_hl[rowx * KPAD + j]);
}

// ---------------- pointwise: internal level (+ h split) ----------------
__global__ void level_kernel(float* __restrict__ h, int l,
                             const float* __restrict__ bih,
                             const float* __restrict__ boh,
                             const float* __restrict__ buh,
                             const float* __restrict__ bfh)
{
    const int nl = 1 << l;
    const int Mh = BATCH << l;
    const int total = Mh * MD;
    const int idx = blockIdx.x * blockDim.x + threadIdx.x;
    if (idx >= total) return;
    const int j = idx % MD;
    const int r = idx / MD;
    const int t = r & (nl - 1);
    const int b = r >> l;
    const int node = (nl - 1) + t;
    const size_t rowx = (size_t)b * NNODES + node;
    const float* gx = g_gates_x + rowx * 1200;
    const float* gio = g_iou + (size_t)r * 900;

    const float i  = sigmoidf(gx[j]       + gio[j]       + bih[j]);
    const float o  = sigmoidf(gx[600 + j] + gio[300 + j] + boh[j]);
    const float u  = tanhf   (gx[900 + j] + gio[600 + j] + buh[j]);
    const float fx = gx[300 + j];
    const float f1 = sigmoidf(fx + g_f[(size_t)r * 300 + j] + bfh[j]);
    const float f2 = sigmoidf(fx + g_f[(size_t)(Mh + r) * 300 + j] + bfh[j]);

    const size_t row1 = (size_t)b * NNODES + 2 * node + 1;
    const float cn = i * u + f1 * g_c[row1 * MD + j] + f2 * g_c[(row1 + 1) * MD + j];
    const float hv = o * tanhf(cn);
    g_c[rowx * MD + j] = cn;
    h[rowx * MD + j] = hv;
    split_bf16(hv, g_hh[rowx * KPAD + j], g_hl[rowx * KPAD + j]);
}

// ---------------- host launch ----------------
extern "C" void kernel_launch(void* const* d_in, const int* in_sizes, int n_in,
                              void* d_out, int out_size)
{
    const float* embs = (const float*)d_in[0];
    const float* Wix = (const float*)d_in[1];
    const float* bix = (const float*)d_in[2];
    const float* Wih = (const float*)d_in[3];
    const float* bih = (const float*)d_in[4];
    const float* Wfx = (const float*)d_in[5];
    const float* bfx = (const float*)d_in[6];
    const float* Wfh = (const float*)d_in[7];
    const float* bfh = (const float*)d_in[8];
    const float* Wox = (const float*)d_in[9];
    const float* box_ = (const float*)d_in[10];
    const float* Woh = (const float*)d_in[11];
    const float* boh = (const float*)d_in[12];
    const float* Wux = (const float*)d_in[13];
    const float* bux = (const float*)d_in[14];
    const float* Wuh = (const float*)d_in[15];
    const float* buh = (const float*)d_in[16];
    float* h = (float*)d_out;

    cudaFuncSetAttribute(gemm_mma,
                         cudaFuncAttributeMaxDynamicSharedMemorySize, SMEM_G);

    float *gx_p, *iou_p, *f_p, *bx_p;
    bf16 *embh_p, *embl_p, *hh_p, *hl_p, *sumh_p, *suml_p;
    bf16 *Wxh_p, *Wxl_p, *Whh_p, *Whl_p, *Wfh_p, *Wfl_p;
    cudaGetSymbolAddress((void**)&gx_p, g_gates_x);
    cudaGetSymbolAddress((void**)&iou_p, g_iou);
    cudaGetSymbolAddress((void**)&f_p, g_f);
    cudaGetSymbolAddress((void**)&bx_p, g_bx);
    cudaGetSymbolAddress((void**)&embh_p, g_embh);
    cudaGetSymbolAddress((void**)&embl_p, g_embl);
    cudaGetSymbolAddress((void**)&hh_p, g_hh);
    cudaGetSymbolAddress((void**)&hl_p, g_hl);
    cudaGetSymbolAddress((void**)&sumh_p, g_sumh);
    cudaGetSymbolAddress((void**)&suml_p, g_suml);
    cudaGetSymbolAddress((void**)&Wxh_p, g_Wxh);
    cudaGetSymbolAddress((void**)&Wxl_p, g_Wxl);
    cudaGetSymbolAddress((void**)&Whh_p, g_Whh);
    cudaGetSymbolAddress((void**)&Whl_p, g_Whl);
    cudaGetSymbolAddress((void**)&Wfh_p, g_Wfh);
    cudaGetSymbolAddress((void**)&Wfl_p, g_Wfl);

    // 1. pack weights (bf16 hi/lo, padded) + bias
    pack_kernel<<<(KPAD * NP_X + 255) / 256, 256>>>(Wix, Wfx, Wox, Wux,
                                                    bix, bfx, box_, bux,
                                                    Wih, Woh, Wuh, Wfh);

    // 2. convert embeddings to bf16 hi/lo
    {
        const long total = (long)TOTAL_ROWS * KPAD;
        convert_embs<<<(int)((total + 255) / 256), 256>>>(embs);
    }

    // 3. input projection: gates_x = embs @ [Wix|Wfx|Wox|Wux] + b
    {
        dim3 grid(1200 / BN + ((1200 % BN) ? 1 : 0), (TOTAL_ROWS + BM - 1) / BM);
        gemm_mma<<<grid, 256, SMEM_G>>>(embh_p, embl_p, Wxh_p, Wxl_p,
                                        gx_p, bx_p,
                                        TOTAL_ROWS, 1200, NP_X, 1200, 0, 0);
    }

    // 4. leaves
    leaf_kernel<<<(BATCH * LEAF_CNT * MD + 255) / 256, 256>>>(h, bih, boh, buh);

    // 5. tree recursion
    for (int l = DEPTH - 2; l >= 0; --l) {
        const int Mh = BATCH << l;
        sumsplit_kernel<<<(Mh * MD + 255) / 256, 256>>>(h, l);
        {
            dim3 grid((900 + BN - 1) / BN, (Mh + BM - 1) / BM);
            gemm_mma<<<grid, 256, SMEM_G>>>(sumh_p, suml_p, Whh_p, Whl_p,
                                            iou_p, nullptr,
                                            Mh, 900, NP_H, 900, 0, 0);
        }
        {
            dim3 grid((300 + BN - 1) / BN, (2 * Mh + BM - 1) / BM);
            gemm_mma<<<grid, 256, SMEM_G>>>(hh_p, hl_p, Wfh_p, Wfl_p,
                                            f_p, nullptr,
                                            2 * Mh, 300, NP_F, 300, 2, l);
        }
        level_kernel<<<(Mh * MD + 255) / 256, 256>>>(h, l, bih, boh, buh, bfh);
    }
}